// round 15
// baseline (speedup 1.0000x reference)
#include <cuda_runtime.h>
#include <cuda_bf16.h>
#include <cstddef>

// ---------------- problem constants ----------------
#define NGg    8
#define NVv    400
#define NCL    1200
#define KLIT   5
#define NNG    (2 * NVv + NCL)
#define D      128
#define LROWS  (NGg * 2 * NVv)        // 6400
#define CROWS  (NGg * NCL)            // 9600
#define NEDGE  (NGg * NCL * KLIT)     // 48000
#define EPG    (NCL * KLIT)
#define ROUNDS 26
#define ADJW   40

typedef __nv_bfloat16 bf16;

// ---------------- device scratch ----------------
__device__ bf16  d_hl[2][LROWS * D];
__device__ bf16  d_hc[2][CROWS * D];
__device__ float d_cl[LROWS * D];
__device__ float d_cc[CROWS * D];
__device__ bf16  d_msg[CROWS * D];
__device__ bf16  d_agg[CROWS * D];
__device__ bf16  d_wb[524288];
__device__ float d_bsum[1024];
__device__ int   d_esrc[NEDGE];
__device__ int   d_adj[LROWS * ADJW];
__device__ int   d_deg[LROWS];

// contiguous weight segments in d_wb (bf16 elems)
#define WB_LMSG   0
#define WB_CMSG   49152
#define WB_CUWIH  98304
#define WB_CUWHH  163840
#define WB_LUWIH  229376
#define WB_LUWHH  360448
#define WB_VOTE0  425984
#define WB_VOTE1  442368
#define WB_TOTAL  458752

// ---------------- helpers ----------------
__device__ __forceinline__ void mma_bf16(float c[4],
    unsigned a0, unsigned a1, unsigned a2, unsigned a3, unsigned b0, unsigned b1)
{
    asm volatile(
        "mma.sync.aligned.m16n8k16.row.col.f32.bf16.bf16.f32 "
        "{%0,%1,%2,%3}, {%4,%5,%6,%7}, {%8,%9}, {%0,%1,%2,%3};"
        : "+f"(c[0]), "+f"(c[1]), "+f"(c[2]), "+f"(c[3])
        : "r"(a0), "r"(a1), "r"(a2), "r"(a3), "r"(b0), "r"(b1));
}
__device__ __forceinline__ void ldsm_x4(unsigned& r0, unsigned& r1,
                                        unsigned& r2, unsigned& r3, const void* p)
{
    unsigned a = (unsigned)__cvta_generic_to_shared(p);
    asm volatile("ldmatrix.sync.aligned.m8n8.x4.shared.b16 {%0,%1,%2,%3}, [%4];"
        : "=r"(r0), "=r"(r1), "=r"(r2), "=r"(r3) : "r"(a));
}
__device__ __forceinline__ void cpasync16(void* smem, const void* g)
{
    unsigned a = (unsigned)__cvta_generic_to_shared(smem);
    asm volatile("cp.async.cg.shared.global [%0], [%1], 16;" :: "r"(a), "l"(g));
}
#define CP_COMMIT() asm volatile("cp.async.commit_group;")
#define CP_WAIT0()  asm volatile("cp.async.wait_group 0;")

__device__ __forceinline__ float sigm(float x) { return 1.f / (1.f + expf(-x)); }
__device__ __forceinline__ int fliprow(int r) {
    int local = r % (2 * NVv);
    return r - local + ((local < NVv) ? local + NVv : local - NVv);
}
__device__ __forceinline__ unsigned pack_bf(float lo, float hi) {
    __nv_bfloat162 p = __floats2bfloat162_rn(lo, hi);
    return *(unsigned*)&p;
}
__device__ __forceinline__ void unpack_bf(unsigned u, float& lo, float& hi) {
    __nv_bfloat162 p = *(__nv_bfloat162*)&u;
    lo = __bfloat162float(p.x);
    hi = __bfloat162float(p.y);
}

// ---------------- one-time setup ----------------
__global__ void cvt_all(
    const float* __restrict__ lmsg_w, const float* __restrict__ cmsg_w,
    const float* __restrict__ cu_wih, const float* __restrict__ cu_whh,
    const float* __restrict__ lu_wih, const float* __restrict__ lu_whh,
    const float* __restrict__ vote_w0, const float* __restrict__ vote_w1,
    const float* __restrict__ cu_bih, const float* __restrict__ cu_bhh,
    const float* __restrict__ lu_bih, const float* __restrict__ lu_bhh,
    bf16* __restrict__ wb, float* __restrict__ bsum)
{
    int i = blockIdx.x * 256 + threadIdx.x;
    if (i < 512)        bsum[i] = cu_bih[i] + cu_bhh[i];
    else if (i < 1024)  bsum[i] = lu_bih[i - 512] + lu_bhh[i - 512];
    if (i >= WB_TOTAL) return;
    float v;
    if      (i < WB_CMSG)   v = lmsg_w[i - WB_LMSG];
    else if (i < WB_CUWIH)  v = cmsg_w[i - WB_CMSG];
    else if (i < WB_CUWHH)  v = cu_wih[i - WB_CUWIH];
    else if (i < WB_LUWIH)  v = cu_whh[i - WB_CUWHH];
    else if (i < WB_LUWHH)  v = lu_wih[i - WB_LUWIH];
    else if (i < WB_VOTE0)  v = lu_whh[i - WB_LUWHH];
    else if (i < WB_VOTE1)  v = vote_w0[i - WB_VOTE0];
    else                    v = vote_w1[i - WB_VOTE1];
    wb[i] = __float2bfloat16_rn(v);
}

__global__ void init_hc(const float* __restrict__ Lw, const float* __restrict__ Lb,
                        const float* __restrict__ Cw, const float* __restrict__ Cb,
                        bf16* __restrict__ hl, bf16* __restrict__ hc,
                        float* __restrict__ cl, float* __restrict__ cc)
{
    int r = blockIdx.x, d = threadIdx.x;
    if (r < LROWS) {
        hl[(size_t)r * D + d] = __float2bfloat16_rn(Lw[d] + Lb[d]);
        cl[(size_t)r * D + d] = 0.f;
    }
    hc[(size_t)r * D + d] = __float2bfloat16_rn(Cw[d] + Cb[d]);
    cc[(size_t)r * D + d] = 0.f;
}

__global__ void compact_edges(const int* __restrict__ edge_src, int* __restrict__ esrc,
                              int* __restrict__ deg)
{
    int e = blockIdx.x * 256 + threadIdx.x;
    if (e < NEDGE) {
        int g = edge_src[e];
        esrc[e] = (g / NNG) * (2 * NVv) + (g % NNG);
    }
    if (e < LROWS) deg[e] = 0;
}

__global__ void fill_adj(const int* __restrict__ esrc,
                         int* __restrict__ adj, int* __restrict__ deg)
{
    int e = blockIdx.x * 256 + threadIdx.x;
    if (e >= NEDGE) return;
    int lit = esrc[e];
    int slot = atomicAdd(&deg[lit], 1);
    if (slot < ADJW) adj[lit * ADJW + slot] = e / KLIT;
}

__global__ void sort_adj(int* __restrict__ adj, int* __restrict__ deg)
{
    int lit = blockIdx.x * 256 + threadIdx.x;
    if (lit >= LROWS) return;
    int n = deg[lit];
    if (n > ADJW) n = ADJW;
    deg[lit] = n;
    int* a = adj + (size_t)lit * ADJW;
    for (int i = 1; i < n; i++) {
        int key = a[i], j = i - 1;
        while (j >= 0 && a[j] > key) { a[j + 1] = a[j]; j--; }
        a[j + 1] = key;
    }
}

// ---------------- fused MLP (bf16, BM=32, 8 warps x 16 cols, ldmatrix) ------------
// smem: X[32][68] + 2 W stages of 128x68 words = 78336 B -> 2 blocks/SM
#define MLP_SMEM ((32 * 68 + 2 * 128 * 68) * 4)
template<int NL>
__global__ __launch_bounds__(256) void mlp_fused(
    const bf16* __restrict__ hin,
    const bf16* __restrict__ W0, const float* __restrict__ B0,
    const bf16* __restrict__ W1, const float* __restrict__ B1,
    const bf16* __restrict__ W2, const float* __restrict__ B2,
    bf16* __restrict__ out, int relu_last)
{
    extern __shared__ __align__(16) unsigned char dynsmem[];
    unsigned (*X)[68] = (unsigned(*)[68])dynsmem;
    unsigned* Wbase   = (unsigned*)(dynsmem + 32 * 68 * 4);

    const int tid  = threadIdx.x;
    const int lane = tid & 31;
    const int warp = tid >> 5;          // 0..7 -> 16-col slice
    const int grp  = lane >> 2;
    const int tig  = lane & 3;
    const int bm   = blockIdx.x * 32;

    // ldmatrix per-lane coordinates
    const int a_row = lane & 15;                              // + mi*16
    const int a_cw  = (lane >> 4) * 4;                        // + ks*8
    const int b_row = warp * 16 + (lane & 7) + ((lane >> 4) & 1) * 8;
    const int b_cw  = ((lane >> 3) & 1) * 4;                  // + ks*8

    const bf16* Wl[3] = { W0, W1, W2 };
    const float* Bl[3] = { B0, B1, B2 };

    {
        const bf16* W = Wl[0];
        #pragma unroll
        for (int t = 0; t < 8; t++) {
            int flat = tid + 256 * t;           // 2048 uint4
            int n = flat >> 4, kb = flat & 15;
            cpasync16(Wbase + (size_t)n * 68 + kb * 4, W + (size_t)n * D + kb * 8);
        }
        CP_COMMIT();
    }
    #pragma unroll
    for (int t = 0; t < 2; t++) {
        int flat = tid + 256 * t;               // 512 uint4
        int r = flat >> 4, kb = flat & 15;
        uint4 v = *(const uint4*)(hin + (size_t)(bm + r) * D + kb * 8);
        *(uint4*)&X[r][kb * 4] = v;
    }

    for (int l = 0; l < NL; l++) {
        CP_WAIT0();
        __syncthreads();
        unsigned (*Wsm)[68] = (unsigned(*)[68])(Wbase + (l & 1) * 128 * 68);
        if (l + 1 < NL) {
            unsigned* nxt = Wbase + ((l + 1) & 1) * 128 * 68;
            const bf16* W = Wl[l + 1];
            #pragma unroll
            for (int t = 0; t < 8; t++) {
                int flat = tid + 256 * t;
                int n = flat >> 4, kb = flat & 15;
                cpasync16(nxt + (size_t)n * 68 + kb * 4, W + (size_t)n * D + kb * 8);
            }
            CP_COMMIT();
        }

        float acc[2][2][4];
        #pragma unroll
        for (int mi = 0; mi < 2; mi++)
            #pragma unroll
            for (int ni = 0; ni < 2; ni++)
                #pragma unroll
                for (int u = 0; u < 4; u++) acc[mi][ni][u] = 0.f;

        #pragma unroll
        for (int ks = 0; ks < 8; ks++) {
            int kk = ks * 8;
            unsigned a[2][4], b[2][2];
            #pragma unroll
            for (int mi = 0; mi < 2; mi++)
                ldsm_x4(a[mi][0], a[mi][1], a[mi][2], a[mi][3],
                        &X[a_row + mi * 16][kk + a_cw]);
            ldsm_x4(b[0][0], b[0][1], b[1][0], b[1][1],
                    &Wsm[b_row][kk + b_cw]);
            #pragma unroll
            for (int mi = 0; mi < 2; mi++)
                #pragma unroll
                for (int ni = 0; ni < 2; ni++)
                    mma_bf16(acc[mi][ni], a[mi][0], a[mi][1], a[mi][2], a[mi][3],
                             b[ni][0], b[ni][1]);
        }
        __syncthreads();

        const float* B = Bl[l];
        int do_relu = (l < NL - 1) || relu_last;
        #pragma unroll
        for (int mi = 0; mi < 2; mi++) {
            #pragma unroll
            for (int ni = 0; ni < 2; ni++) {
                int r0 = mi * 16 + grp;
                int c0 = warp * 16 + ni * 8 + 2 * tig;
                #pragma unroll
                for (int h = 0; h < 2; h++) {
                    int r = r0 + h * 8;
                    float v0 = acc[mi][ni][h * 2 + 0] + B[c0];
                    float v1 = acc[mi][ni][h * 2 + 1] + B[c0 + 1];
                    if (do_relu) { v0 = fmaxf(v0, 0.f); v1 = fmaxf(v1, 0.f); }
                    unsigned p = pack_bf(v0, v1);
                    if (l == NL - 1)
                        *(unsigned*)(out + (size_t)(bm + r) * D + c0) = p;
                    else
                        X[r][c0 >> 1] = p;
                }
            }
        }
    }
}

// ---------------- clause aggregation (4 rows/block, uint loads) ----------------
__global__ void clause_agg(const unsigned* __restrict__ msg, const int* __restrict__ esrc,
                           unsigned* __restrict__ agg)
{
    int t = threadIdx.x;
    int cr = blockIdx.x * 4 + (t >> 6);
    int w  = t & 63;
    const int* es = esrc + cr * KLIT;
    float s0 = 0.f, s1 = 0.f;
    #pragma unroll
    for (int k = 0; k < KLIT; k++) {
        float a, b;
        unpack_bf(msg[(size_t)es[k] * 64 + w], a, b);
        s0 += a; s1 += b;
    }
    agg[(size_t)cr * 64 + w] = pack_bf(s0, s1);
}

// ---------------- literal aggregation (ELL, 4 rows/block, uint loads) -------------
__global__ void lit_agg(const unsigned* __restrict__ msg, const int* __restrict__ adj,
                        const int* __restrict__ deg, unsigned* __restrict__ agg)
{
    int t = threadIdx.x;
    int r = blockIdx.x * 4 + (t >> 6);
    int w = t & 63;
    int n = deg[r];
    const int* ad = adj + (size_t)r * ADJW;
    float s0 = 0.f, s1 = 0.f;
    for (int e = 0; e < n; e++) {
        float a, b;
        unpack_bf(msg[(size_t)ad[e] * 64 + w], a, b);
        s0 += a; s1 += b;
    }
    agg[(size_t)r * 64 + w] = pack_bf(s0, s1);
}

// ---------------- gate GEMM: 64x128 tile, ldmatrix, cp.async DB, LSTM epilogue ----
#define GATE_STAGE ((64 * 36 + 128 * 36) * 4)
#define GATE_SMEM  (2 * GATE_STAGE)
template<int KTOT, int MODE>
__global__ __launch_bounds__(256) void gate_lstm(
    const bf16* __restrict__ agg, const bf16* __restrict__ hold,
    const bf16* __restrict__ Wih, int ldwih,
    const bf16* __restrict__ Whh,
    const float* __restrict__ bsum,
    bf16* __restrict__ hnew, float* __restrict__ cst)
{
    extern __shared__ __align__(16) unsigned char dynsmem[];

    const int tid  = threadIdx.x;
    const int lane = tid & 31;
    const int warp = tid >> 5;
    const int wr   = warp & 1;
    const int wc   = warp >> 1;
    const int grp  = lane >> 2;
    const int tig  = lane & 3;
    const int bm   = blockIdx.x * 64;
    const int dd0  = blockIdx.y * 32;

    const int a_lr = tid >> 3;
    const int a_kb = tid & 7;
    const int w_kb = tid & 7;

    const int fa_row = wr * 32 + (lane & 15);
    const int fa_cw  = (lane >> 4) * 4;
    const int fb_row = wc * 32 + (lane & 7) + ((lane >> 4) & 1) * 8;
    const int fb_cw  = ((lane >> 3) & 1) * 4;

    auto srcA = [&](int ch, int t) -> const bf16* {
        int k0 = ch * 64;
        int lr = a_lr + 32 * t;
        int row = bm + lr;
        int k = k0 + a_kb * 8;
        if (MODE == 0) {
            if (k0 < 128) return agg  + (size_t)row * D + k;
            else          return hold + (size_t)row * D + (k - 128);
        } else {
            if (k0 < 128)      return agg  + (size_t)row * D + k;
            else if (k0 < 256) return hold + (size_t)fliprow(row) * D + (k - 128);
            else               return hold + (size_t)row * D + (k - 256);
        }
    };
    auto srcW = [&](int ch, int t) -> const bf16* {
        int k0 = ch * 64;
        int flat = tid + 256 * t;
        int wrow = flat >> 3;
        int k = k0 + w_kb * 8;
        int n = (wrow >> 5) * 128 + dd0 + (wrow & 31);
        if (k0 < KTOT - 128) return Wih + (size_t)n * ldwih + k;
        else                 return Whh + (size_t)n * D + (k - (KTOT - 128));
    };
    auto dstA = [&](int st, int t) -> void* {
        unsigned (*As)[36] = (unsigned(*)[36])(dynsmem + st * GATE_STAGE);
        int lr = a_lr + 32 * t;
        return &As[lr][a_kb * 4];
    };
    auto dstW = [&](int st, int t) -> void* {
        unsigned (*Ws)[36] = (unsigned(*)[36])(dynsmem + st * GATE_STAGE + 64 * 36 * 4);
        int flat = tid + 256 * t;
        int wrow = flat >> 3;
        return &Ws[wrow][w_kb * 4];
    };

    float acc[2][4][4];
    #pragma unroll
    for (int mi = 0; mi < 2; mi++)
        #pragma unroll
        for (int ni = 0; ni < 4; ni++)
            #pragma unroll
            for (int u = 0; u < 4; u++) acc[mi][ni][u] = 0.f;

    const int NCH = KTOT / 64;
    #pragma unroll
    for (int t = 0; t < 2; t++) cpasync16(dstA(0, t), srcA(0, t));
    #pragma unroll
    for (int t = 0; t < 4; t++) cpasync16(dstW(0, t), srcW(0, t));
    CP_COMMIT();
    CP_WAIT0();
    __syncthreads();

    for (int ch = 0; ch < NCH; ch++) {
        const int st = ch & 1;
        const bool more = (ch + 1 < NCH);
        if (more) {
            #pragma unroll
            for (int t = 0; t < 2; t++) cpasync16(dstA(1 - st, t), srcA(ch + 1, t));
            #pragma unroll
            for (int t = 0; t < 4; t++) cpasync16(dstW(1 - st, t), srcW(ch + 1, t));
            CP_COMMIT();
        }
        unsigned (*As)[36] = (unsigned(*)[36])(dynsmem + st * GATE_STAGE);
        unsigned (*Ws)[36] = (unsigned(*)[36])(dynsmem + st * GATE_STAGE + 64 * 36 * 4);
        #pragma unroll
        for (int ks = 0; ks < 4; ks++) {
            int kk = ks * 8;
            unsigned a[2][4], b[4][2];
            #pragma unroll
            for (int mi = 0; mi < 2; mi++)
                ldsm_x4(a[mi][0], a[mi][1], a[mi][2], a[mi][3],
                        &As[fa_row + mi * 16][kk + fa_cw]);
            #pragma unroll
            for (int n2 = 0; n2 < 2; n2++)
                ldsm_x4(b[n2 * 2][0], b[n2 * 2][1], b[n2 * 2 + 1][0], b[n2 * 2 + 1][1],
                        &Ws[fb_row + n2 * 16][kk + fb_cw]);
            #pragma unroll
            for (int mi = 0; mi < 2; mi++)
                #pragma unroll
                for (int ni = 0; ni < 4; ni++)
                    mma_bf16(acc[mi][ni], a[mi][0], a[mi][1], a[mi][2], a[mi][3],
                             b[ni][0], b[ni][1]);
        }
        if (more) CP_WAIT0();
        __syncthreads();
    }

    float (*gbuf)[132] = (float(*)[132])dynsmem;
    #pragma unroll
    for (int mi = 0; mi < 2; mi++) {
        #pragma unroll
        for (int ni = 0; ni < 4; ni++) {
            int r0 = wr * 32 + mi * 16 + grp;
            int c0 = wc * 32 + ni * 8 + 2 * tig;
            gbuf[r0    ][c0    ] = acc[mi][ni][0];
            gbuf[r0    ][c0 + 1] = acc[mi][ni][1];
            gbuf[r0 + 8][c0    ] = acc[mi][ni][2];
            gbuf[r0 + 8][c0 + 1] = acc[mi][ni][3];
        }
    }
    __syncthreads();

    int ddl = tid & 31;
    int rl0 = tid >> 5;
    int dd  = dd0 + ddl;
    float bi0 = bsum[0 * 128 + dd];
    float bi1 = bsum[1 * 128 + dd];
    float bi2 = bsum[2 * 128 + dd];
    float bi3 = bsum[3 * 128 + dd];
    #pragma unroll
    for (int it = 0; it < 8; it++) {
        int lrow = it * 8 + rl0;
        int row  = bm + lrow;
        float gi = gbuf[lrow][0 * 32 + ddl] + bi0;
        float gf = gbuf[lrow][1 * 32 + ddl] + bi1;
        float gg = gbuf[lrow][2 * 32 + ddl] + bi2;
        float go = gbuf[lrow][3 * 32 + ddl] + bi3;
        size_t off = (size_t)row * D + dd;
        float c2 = sigm(gf) * cst[off] + sigm(gi) * tanhf(gg);
        cst[off] = c2;
        hnew[off] = __float2bfloat16_rn(sigm(go) * tanhf(c2));
    }
}

// ---------------- vote tail: per-row dot + per-graph mean, one kernel -------------
__global__ void vote_tail(const bf16* __restrict__ v2, const float* __restrict__ w2,
                          const float* __restrict__ b2, const int* __restrict__ n_vars,
                          float* __restrict__ out)
{
    int g = blockIdx.x;
    int warp = threadIdx.x >> 5;
    int lane = threadIdx.x & 31;
    __shared__ float wsh[128];
    for (int i = threadIdx.x; i < 128; i += 256) wsh[i] = w2[i];
    __syncthreads();
    float gsum = 0.f;
    for (int row = g * 2 * NVv + warp; row < (g + 1) * 2 * NVv; row += 8) {
        float p = 0.f;
        #pragma unroll
        for (int w = 0; w < 4; w++) {
            int d = lane + w * 32;
            p += __bfloat162float(v2[(size_t)row * D + d]) * wsh[d];
        }
        #pragma unroll
        for (int s = 16; s > 0; s >>= 1) p += __shfl_down_sync(0xffffffff, p, s);
        if (lane == 0) gsum += p + b2[0];
    }
    __shared__ float red[8];
    if (lane == 0) red[warp] = gsum;
    __syncthreads();
    if (threadIdx.x == 0) {
        float s = 0.f;
        for (int i = 0; i < 8; i++) s += red[i];
        out[g] = s / (2.f * (float)n_vars[g]);
    }
}

// ---------------- host orchestration ----------------
extern "C" void kernel_launch(void* const* d_in, const int* in_sizes, int n_in,
                              void* d_out, int out_size)
{
    const int* edge_src   = (const int*)d_in[0];
    const int* n_vars     = (const int*)d_in[6];
    const float* L_init_w = (const float*)d_in[7];
    const float* L_init_b = (const float*)d_in[8];
    const float* C_init_w = (const float*)d_in[9];
    const float* C_init_b = (const float*)d_in[10];
    const float* lmsg_w   = (const float*)d_in[11];
    const float* lmsg_b   = (const float*)d_in[12];
    const float* cmsg_w   = (const float*)d_in[13];
    const float* cmsg_b   = (const float*)d_in[14];
    const float* lu_wih   = (const float*)d_in[15];
    const float* lu_whh   = (const float*)d_in[16];
    const float* lu_bih   = (const float*)d_in[17];
    const float* lu_bhh   = (const float*)d_in[18];
    const float* cu_wih   = (const float*)d_in[19];
    const float* cu_whh   = (const float*)d_in[20];
    const float* cu_bih   = (const float*)d_in[21];
    const float* cu_bhh   = (const float*)d_in[22];
    const float* vote_w0  = (const float*)d_in[23];
    const float* vote_b0  = (const float*)d_in[24];
    const float* vote_w1  = (const float*)d_in[25];
    const float* vote_b1  = (const float*)d_in[26];
    const float* vote_w2  = (const float*)d_in[27];
    const float* vote_b2  = (const float*)d_in[28];

    bf16 *hl0, *hl1, *hc0, *hc1, *msg, *agg, *wb;
    float *cl, *cc, *bsum;
    int *esrc, *adj, *deg;
    cudaGetSymbolAddress((void**)&hl0,  d_hl);      hl1 = hl0 + LROWS * D;
    cudaGetSymbolAddress((void**)&hc0,  d_hc);      hc1 = hc0 + CROWS * D;
    cudaGetSymbolAddress((void**)&cl,   d_cl);
    cudaGetSymbolAddress((void**)&cc,   d_cc);
    cudaGetSymbolAddress((void**)&msg,  d_msg);
    cudaGetSymbolAddress((void**)&agg,  d_agg);
    cudaGetSymbolAddress((void**)&wb,   d_wb);
    cudaGetSymbolAddress((void**)&bsum, d_bsum);
    cudaGetSymbolAddress((void**)&esrc, d_esrc);
    cudaGetSymbolAddress((void**)&adj,  d_adj);
    cudaGetSymbolAddress((void**)&deg,  d_deg);

    cudaFuncSetAttribute(mlp_fused<3>, cudaFuncAttributeMaxDynamicSharedMemorySize, MLP_SMEM);
    cudaFuncSetAttribute(mlp_fused<2>, cudaFuncAttributeMaxDynamicSharedMemorySize, MLP_SMEM);
    cudaFuncSetAttribute(gate_lstm<256, 0>, cudaFuncAttributeMaxDynamicSharedMemorySize, GATE_SMEM);
    cudaFuncSetAttribute(gate_lstm<384, 1>, cudaFuncAttributeMaxDynamicSharedMemorySize, GATE_SMEM);

    cvt_all<<<(WB_TOTAL + 255) / 256, 256>>>(lmsg_w, cmsg_w, cu_wih, cu_whh,
                                             lu_wih, lu_whh, vote_w0, vote_w1,
                                             cu_bih, cu_bhh, lu_bih, lu_bhh, wb, bsum);
    compact_edges<<<(NEDGE + 255) / 256, 256>>>(edge_src, esrc, deg);
    init_hc<<<CROWS, D>>>(L_init_w, L_init_b, C_init_w, C_init_b, hl0, hc0, cl, cc);
    fill_adj<<<(NEDGE + 255) / 256, 256>>>(esrc, adj, deg);
    sort_adj<<<(LROWS + 255) / 256, 256>>>(adj, deg);

    bf16* hls[2] = { hl0, hl1 };
    bf16* hcs[2] = { hc0, hc1 };

    for (int r = 0; r < ROUNDS; r++) {
        bf16* hlc = hls[r & 1];
        bf16* hln = hls[(r + 1) & 1];
        bf16* hcc = hcs[r & 1];
        bf16* hcn = hcs[(r + 1) & 1];

        mlp_fused<3><<<LROWS / 32, 256, MLP_SMEM>>>(hlc,
            wb + WB_LMSG + 0 * D * D, lmsg_b + 0 * D,
            wb + WB_LMSG + 1 * D * D, lmsg_b + 1 * D,
            wb + WB_LMSG + 2 * D * D, lmsg_b + 2 * D, msg, 0);
        clause_agg<<<CROWS / 4, 256>>>((const unsigned*)msg, esrc, (unsigned*)agg);
        gate_lstm<256, 0><<<dim3(CROWS / 64, 4), 256, GATE_SMEM>>>(agg, hcc,
            wb + WB_CUWIH, D, wb + WB_CUWHH, bsum, hcn, cc);
        mlp_fused<3><<<CROWS / 32, 256, MLP_SMEM>>>(hcn,
            wb + WB_CMSG + 0 * D * D, cmsg_b + 0 * D,
            wb + WB_CMSG + 1 * D * D, cmsg_b + 1 * D,
            wb + WB_CMSG + 2 * D * D, cmsg_b + 2 * D, msg, 0);
        lit_agg<<<LROWS / 4, 256>>>((const unsigned*)msg, adj, deg, (unsigned*)agg);
        gate_lstm<384, 1><<<dim3(LROWS / 64, 4), 256, GATE_SMEM>>>(agg, hlc,
            wb + WB_LUWIH, 2 * D, wb + WB_LUWHH, bsum + 512, hln, cl);
    }

    bf16* hfin = hls[ROUNDS & 1];
    mlp_fused<2><<<LROWS / 32, 256, MLP_SMEM>>>(hfin,
        wb + WB_VOTE0, vote_b0, wb + WB_VOTE1, vote_b1, wb + WB_VOTE1, vote_b1, msg, 1);
    vote_tail<<<NGg, 256>>>(msg, vote_w2, vote_b2, n_vars, (float*)d_out);

    (void)in_sizes; (void)n_in; (void)out_size;
}

// round 16
// speedup vs baseline: 1.1051x; 1.1051x over previous
#include <cuda_runtime.h>
#include <cuda_bf16.h>
#include <cstddef>

// ---------------- problem constants ----------------
#define NGg    8
#define NVv    400
#define NCL    1200
#define KLIT   5
#define NNG    (2 * NVv + NCL)
#define D      128
#define LROWS  (NGg * 2 * NVv)        // 6400
#define CROWS  (NGg * NCL)            // 9600
#define NEDGE  (NGg * NCL * KLIT)     // 48000
#define EPG    (NCL * KLIT)
#define ROUNDS 26
#define ADJW   40

typedef __nv_bfloat16 bf16;

// ---------------- device scratch ----------------
__device__ bf16  d_hl[2][LROWS * D];
__device__ bf16  d_hc[2][CROWS * D];
__device__ float d_cl[LROWS * D];
__device__ float d_cc[CROWS * D];
__device__ bf16  d_msg[CROWS * D];
__device__ bf16  d_agg[CROWS * D];
__device__ bf16  d_wb[524288];
__device__ float d_bsum[1024];
__device__ int   d_esrc[NEDGE];
__device__ int   d_adj[LROWS * ADJW];
__device__ int   d_deg[LROWS];

// contiguous weight segments in d_wb (bf16 elems)
#define WB_LMSG   0
#define WB_CMSG   49152
#define WB_CUWIH  98304
#define WB_CUWHH  163840
#define WB_LUWIH  229376
#define WB_LUWHH  360448
#define WB_VOTE0  425984
#define WB_VOTE1  442368
#define WB_TOTAL  458752

// ---------------- helpers ----------------
__device__ __forceinline__ void mma_bf16(float c[4],
    unsigned a0, unsigned a1, unsigned a2, unsigned a3, unsigned b0, unsigned b1)
{
    asm volatile(
        "mma.sync.aligned.m16n8k16.row.col.f32.bf16.bf16.f32 "
        "{%0,%1,%2,%3}, {%4,%5,%6,%7}, {%8,%9}, {%0,%1,%2,%3};"
        : "+f"(c[0]), "+f"(c[1]), "+f"(c[2]), "+f"(c[3])
        : "r"(a0), "r"(a1), "r"(a2), "r"(a3), "r"(b0), "r"(b1));
}
__device__ __forceinline__ void ldsm_x4(unsigned& r0, unsigned& r1,
                                        unsigned& r2, unsigned& r3, const void* p)
{
    unsigned a = (unsigned)__cvta_generic_to_shared(p);
    asm volatile("ldmatrix.sync.aligned.m8n8.x4.shared.b16 {%0,%1,%2,%3}, [%4];"
        : "=r"(r0), "=r"(r1), "=r"(r2), "=r"(r3) : "r"(a));
}
__device__ __forceinline__ void cpasync16(void* smem, const void* g)
{
    unsigned a = (unsigned)__cvta_generic_to_shared(smem);
    asm volatile("cp.async.cg.shared.global [%0], [%1], 16;" :: "r"(a), "l"(g));
}
#define CP_COMMIT() asm volatile("cp.async.commit_group;")
#define CP_WAIT0()  asm volatile("cp.async.wait_group 0;")

__device__ __forceinline__ float sigm(float x) { return 1.f / (1.f + expf(-x)); }
__device__ __forceinline__ int fliprow(int r) {
    int local = r % (2 * NVv);
    return r - local + ((local < NVv) ? local + NVv : local - NVv);
}
__device__ __forceinline__ unsigned pack_bf(float lo, float hi) {
    __nv_bfloat162 p = __floats2bfloat162_rn(lo, hi);
    return *(unsigned*)&p;
}
__device__ __forceinline__ void unpack_bf(unsigned u, float& lo, float& hi) {
    __nv_bfloat162 p = *(__nv_bfloat162*)&u;
    lo = __bfloat162float(p.x);
    hi = __bfloat162float(p.y);
}

// ---------------- one-time setup ----------------
__global__ void cvt_all(
    const float* __restrict__ lmsg_w, const float* __restrict__ cmsg_w,
    const float* __restrict__ cu_wih, const float* __restrict__ cu_whh,
    const float* __restrict__ lu_wih, const float* __restrict__ lu_whh,
    const float* __restrict__ vote_w0, const float* __restrict__ vote_w1,
    const float* __restrict__ cu_bih, const float* __restrict__ cu_bhh,
    const float* __restrict__ lu_bih, const float* __restrict__ lu_bhh,
    bf16* __restrict__ wb, float* __restrict__ bsum)
{
    int i = blockIdx.x * 256 + threadIdx.x;
    if (i < 512)        bsum[i] = cu_bih[i] + cu_bhh[i];
    else if (i < 1024)  bsum[i] = lu_bih[i - 512] + lu_bhh[i - 512];
    if (i >= WB_TOTAL) return;
    float v;
    if      (i < WB_CMSG)   v = lmsg_w[i - WB_LMSG];
    else if (i < WB_CUWIH)  v = cmsg_w[i - WB_CMSG];
    else if (i < WB_CUWHH)  v = cu_wih[i - WB_CUWIH];
    else if (i < WB_LUWIH)  v = cu_whh[i - WB_CUWHH];
    else if (i < WB_LUWHH)  v = lu_wih[i - WB_LUWIH];
    else if (i < WB_VOTE0)  v = lu_whh[i - WB_LUWHH];
    else if (i < WB_VOTE1)  v = vote_w0[i - WB_VOTE0];
    else                    v = vote_w1[i - WB_VOTE1];
    wb[i] = __float2bfloat16_rn(v);
}

__global__ void init_hc(const float* __restrict__ Lw, const float* __restrict__ Lb,
                        const float* __restrict__ Cw, const float* __restrict__ Cb,
                        bf16* __restrict__ hl, bf16* __restrict__ hc,
                        float* __restrict__ cl, float* __restrict__ cc)
{
    int r = blockIdx.x, d = threadIdx.x;
    if (r < LROWS) {
        hl[(size_t)r * D + d] = __float2bfloat16_rn(Lw[d] + Lb[d]);
        cl[(size_t)r * D + d] = 0.f;
    }
    hc[(size_t)r * D + d] = __float2bfloat16_rn(Cw[d] + Cb[d]);
    cc[(size_t)r * D + d] = 0.f;
}

__global__ void compact_edges(const int* __restrict__ edge_src, int* __restrict__ esrc,
                              int* __restrict__ deg)
{
    int e = blockIdx.x * 256 + threadIdx.x;
    if (e < NEDGE) {
        int g = edge_src[e];
        esrc[e] = (g / NNG) * (2 * NVv) + (g % NNG);
    }
    if (e < LROWS) deg[e] = 0;
}

__global__ void fill_adj(const int* __restrict__ esrc,
                         int* __restrict__ adj, int* __restrict__ deg)
{
    int e = blockIdx.x * 256 + threadIdx.x;
    if (e >= NEDGE) return;
    int lit = esrc[e];
    int slot = atomicAdd(&deg[lit], 1);
    if (slot < ADJW) adj[lit * ADJW + slot] = e / KLIT;
}

__global__ void sort_adj(int* __restrict__ adj, int* __restrict__ deg)
{
    int lit = blockIdx.x * 256 + threadIdx.x;
    if (lit >= LROWS) return;
    int n = deg[lit];
    if (n > ADJW) n = ADJW;
    deg[lit] = n;
    int* a = adj + (size_t)lit * ADJW;
    for (int i = 1; i < n; i++) {
        int key = a[i], j = i - 1;
        while (j >= 0 && a[j] > key) { a[j + 1] = a[j]; j--; }
        a[j + 1] = key;
    }
}

// ---------------- fused MLP (bf16, BM=64, ldmatrix, cp.async W pipeline) ----------
#define MLP_SMEM ((64 * 68 + 2 * 128 * 68) * 4)
template<int NL>
__global__ __launch_bounds__(256) void mlp_fused(
    const bf16* __restrict__ hin,
    const bf16* __restrict__ W0, const float* __restrict__ B0,
    const bf16* __restrict__ W1, const float* __restrict__ B1,
    const bf16* __restrict__ W2, const float* __restrict__ B2,
    bf16* __restrict__ out, int relu_last)
{
    extern __shared__ __align__(16) unsigned char dynsmem[];
    unsigned (*X)[68] = (unsigned(*)[68])dynsmem;
    unsigned* Wbase   = (unsigned*)(dynsmem + 64 * 68 * 4);

    const int tid  = threadIdx.x;
    const int lane = tid & 31;
    const int warp = tid >> 5;
    const int wr   = warp & 1;
    const int wc   = warp >> 1;
    const int grp  = lane >> 2;
    const int tig  = lane & 3;
    const int bm   = blockIdx.x * 64;

    const int a_row = wr * 32 + (lane & 15);
    const int a_cw  = (lane >> 4) * 4;
    const int b_row = wc * 32 + (lane & 7) + ((lane >> 4) & 1) * 8;
    const int b_cw  = ((lane >> 3) & 1) * 4;

    const bf16* Wl[3] = { W0, W1, W2 };
    const float* Bl[3] = { B0, B1, B2 };

    {
        const bf16* W = Wl[0];
        #pragma unroll
        for (int t = 0; t < 8; t++) {
            int flat = tid + 256 * t;
            int n = flat >> 4, kb = flat & 15;
            cpasync16(Wbase + (size_t)n * 68 + kb * 4, W + (size_t)n * D + kb * 8);
        }
        CP_COMMIT();
    }
    #pragma unroll
    for (int t = 0; t < 4; t++) {
        int flat = tid + 256 * t;
        int r = flat >> 4, kb = flat & 15;
        uint4 v = *(const uint4*)(hin + (size_t)(bm + r) * D + kb * 8);
        *(uint4*)&X[r][kb * 4] = v;
    }

    for (int l = 0; l < NL; l++) {
        CP_WAIT0();
        __syncthreads();
        unsigned (*Wsm)[68] = (unsigned(*)[68])(Wbase + (l & 1) * 128 * 68);
        if (l + 1 < NL) {
            unsigned* nxt = Wbase + ((l + 1) & 1) * 128 * 68;
            const bf16* W = Wl[l + 1];
            #pragma unroll
            for (int t = 0; t < 8; t++) {
                int flat = tid + 256 * t;
                int n = flat >> 4, kb = flat & 15;
                cpasync16(nxt + (size_t)n * 68 + kb * 4, W + (size_t)n * D + kb * 8);
            }
            CP_COMMIT();
        }

        float acc[2][4][4];
        #pragma unroll
        for (int mi = 0; mi < 2; mi++)
            #pragma unroll
            for (int ni = 0; ni < 4; ni++)
                #pragma unroll
                for (int u = 0; u < 4; u++) acc[mi][ni][u] = 0.f;

        #pragma unroll
        for (int ks = 0; ks < 8; ks++) {
            int kk = ks * 8;
            unsigned a[2][4], b[4][2];
            #pragma unroll
            for (int mi = 0; mi < 2; mi++)
                ldsm_x4(a[mi][0], a[mi][1], a[mi][2], a[mi][3],
                        &X[a_row + mi * 16][kk + a_cw]);
            #pragma unroll
            for (int n2 = 0; n2 < 2; n2++)
                ldsm_x4(b[n2 * 2][0], b[n2 * 2][1], b[n2 * 2 + 1][0], b[n2 * 2 + 1][1],
                        &Wsm[b_row + n2 * 16][kk + b_cw]);
            #pragma unroll
            for (int mi = 0; mi < 2; mi++)
                #pragma unroll
                for (int ni = 0; ni < 4; ni++)
                    mma_bf16(acc[mi][ni], a[mi][0], a[mi][1], a[mi][2], a[mi][3],
                             b[ni][0], b[ni][1]);
        }
        __syncthreads();

        const float* B = Bl[l];
        int do_relu = (l < NL - 1) || relu_last;
        #pragma unroll
        for (int mi = 0; mi < 2; mi++) {
            #pragma unroll
            for (int ni = 0; ni < 4; ni++) {
                int r0 = wr * 32 + mi * 16 + grp;
                int c0 = wc * 32 + ni * 8 + 2 * tig;
                #pragma unroll
                for (int h = 0; h < 2; h++) {
                    int r = r0 + h * 8;
                    float v0 = acc[mi][ni][h * 2 + 0] + B[c0];
                    float v1 = acc[mi][ni][h * 2 + 1] + B[c0 + 1];
                    if (do_relu) { v0 = fmaxf(v0, 0.f); v1 = fmaxf(v1, 0.f); }
                    unsigned p = pack_bf(v0, v1);
                    if (l == NL - 1)
                        *(unsigned*)(out + (size_t)(bm + r) * D + c0) = p;
                    else
                        X[r][c0 >> 1] = p;
                }
            }
        }
    }
}

// ---------------- clause aggregation (4 rows/block, uint loads) ----------------
__global__ void clause_agg(const unsigned* __restrict__ msg, const int* __restrict__ esrc,
                           unsigned* __restrict__ agg)
{
    int t = threadIdx.x;
    int cr = blockIdx.x * 4 + (t >> 6);
    int w  = t & 63;
    const int* es = esrc + cr * KLIT;
    float s0 = 0.f, s1 = 0.f;
    #pragma unroll
    for (int k = 0; k < KLIT; k++) {
        float a, b;
        unpack_bf(msg[(size_t)es[k] * 64 + w], a, b);
        s0 += a; s1 += b;
    }
    agg[(size_t)cr * 64 + w] = pack_bf(s0, s1);
}

// ---------------- literal aggregation (ELL, 4 rows/block, uint loads) -------------
__global__ void lit_agg(const unsigned* __restrict__ msg, const int* __restrict__ adj,
                        const int* __restrict__ deg, unsigned* __restrict__ agg)
{
    int t = threadIdx.x;
    int r = blockIdx.x * 4 + (t >> 6);
    int w = t & 63;
    int n = deg[r];
    const int* ad = adj + (size_t)r * ADJW;
    float s0 = 0.f, s1 = 0.f;
    for (int e = 0; e < n; e++) {
        float a, b;
        unpack_bf(msg[(size_t)ad[e] * 64 + w], a, b);
        s0 += a; s1 += b;
    }
    agg[(size_t)r * 64 + w] = pack_bf(s0, s1);
}

// ---------------- gate GEMM: 64x128 tile, gate-major B tiles, in-register LSTM ----
// W smem row permutation: srow = (ddlocal>>3)*32 + gate*8 + (ddlocal&7)
// -> warp wc's x4 fragment at &Ws[wc*32 + lane] yields tiles = gates 0..3 for
//    dd slice [dd0 + wc*8, +8). acc[mi][gate] holds all 4 gates for one (row,dd2).
#define GATE_STAGE ((64 * 36 + 128 * 36) * 4)
#define GATE_SMEM  (2 * GATE_STAGE)
template<int KTOT, int MODE>
__global__ __launch_bounds__(256) void gate_lstm(
    const bf16* __restrict__ agg, const bf16* __restrict__ hold,
    const bf16* __restrict__ Wih, int ldwih,
    const bf16* __restrict__ Whh,
    const float* __restrict__ bsum,
    bf16* __restrict__ hnew, float* __restrict__ cst)
{
    extern __shared__ __align__(16) unsigned char dynsmem[];

    const int tid  = threadIdx.x;
    const int lane = tid & 31;
    const int warp = tid >> 5;
    const int wr   = warp & 1;
    const int wc   = warp >> 1;
    const int grp  = lane >> 2;
    const int tig  = lane & 3;
    const int bm   = blockIdx.x * 64;
    const int dd0  = blockIdx.y * 32;

    const int a_lr = tid >> 3;
    const int a_kb = tid & 7;
    const int w_kb = tid & 7;

    const int fa_row = wr * 32 + (lane & 15);
    const int fa_cw  = (lane >> 4) * 4;

    auto srcA = [&](int ch, int t) -> const bf16* {
        int k0 = ch * 64;
        int lr = a_lr + 32 * t;
        int row = bm + lr;
        int k = k0 + a_kb * 8;
        if (MODE == 0) {
            if (k0 < 128) return agg  + (size_t)row * D + k;
            else          return hold + (size_t)row * D + (k - 128);
        } else {
            if (k0 < 128)      return agg  + (size_t)row * D + k;
            else if (k0 < 256) return hold + (size_t)fliprow(row) * D + (k - 128);
            else               return hold + (size_t)row * D + (k - 256);
        }
    };
    auto srcW = [&](int ch, int t) -> const bf16* {
        int k0 = ch * 64;
        int flat = tid + 256 * t;
        int wrow = flat >> 3;                 // gate*32 + ddlocal
        int k = k0 + w_kb * 8;
        int n = (wrow >> 5) * 128 + dd0 + (wrow & 31);
        if (k0 < KTOT - 128) return Wih + (size_t)n * ldwih + k;
        else                 return Whh + (size_t)n * D + (k - (KTOT - 128));
    };
    auto dstA = [&](int st, int t) -> void* {
        unsigned (*As)[36] = (unsigned(*)[36])(dynsmem + st * GATE_STAGE);
        int lr = a_lr + 32 * t;
        return &As[lr][a_kb * 4];
    };
    auto dstW = [&](int st, int t) -> void* {
        unsigned (*Ws)[36] = (unsigned(*)[36])(dynsmem + st * GATE_STAGE + 64 * 36 * 4);
        int flat = tid + 256 * t;
        int wrow = flat >> 3;
        int gate = wrow >> 5, local = wrow & 31;
        int srow = (local >> 3) * 32 + gate * 8 + (local & 7);
        return &Ws[srow][w_kb * 4];
    };

    float acc[2][4][4];
    #pragma unroll
    for (int mi = 0; mi < 2; mi++)
        #pragma unroll
        for (int g = 0; g < 4; g++)
            #pragma unroll
            for (int u = 0; u < 4; u++) acc[mi][g][u] = 0.f;

    const int NCH = KTOT / 64;
    #pragma unroll
    for (int t = 0; t < 2; t++) cpasync16(dstA(0, t), srcA(0, t));
    #pragma unroll
    for (int t = 0; t < 4; t++) cpasync16(dstW(0, t), srcW(0, t));
    CP_COMMIT();
    CP_WAIT0();
    __syncthreads();

    for (int ch = 0; ch < NCH; ch++) {
        const int st = ch & 1;
        const bool more = (ch + 1 < NCH);
        if (more) {
            #pragma unroll
            for (int t = 0; t < 2; t++) cpasync16(dstA(1 - st, t), srcA(ch + 1, t));
            #pragma unroll
            for (int t = 0; t < 4; t++) cpasync16(dstW(1 - st, t), srcW(ch + 1, t));
            CP_COMMIT();
        }
        unsigned (*As)[36] = (unsigned(*)[36])(dynsmem + st * GATE_STAGE);
        unsigned (*Ws)[36] = (unsigned(*)[36])(dynsmem + st * GATE_STAGE + 64 * 36 * 4);
        #pragma unroll
        for (int ks = 0; ks < 4; ks++) {
            int kk = ks * 8;
            unsigned a[2][4], blo[4], bhi[4];
            #pragma unroll
            for (int mi = 0; mi < 2; mi++)
                ldsm_x4(a[mi][0], a[mi][1], a[mi][2], a[mi][3],
                        &As[fa_row + mi * 16][kk + fa_cw]);
            ldsm_x4(blo[0], blo[1], blo[2], blo[3], &Ws[wc * 32 + lane][kk]);
            ldsm_x4(bhi[0], bhi[1], bhi[2], bhi[3], &Ws[wc * 32 + lane][kk + 4]);
            #pragma unroll
            for (int mi = 0; mi < 2; mi++)
                #pragma unroll
                for (int g = 0; g < 4; g++)
                    mma_bf16(acc[mi][g], a[mi][0], a[mi][1], a[mi][2], a[mi][3],
                             blo[g], bhi[g]);
        }
        if (more) CP_WAIT0();
        __syncthreads();
    }

    // ---- in-register LSTM epilogue ----
    const int ddb = dd0 + wc * 8 + 2 * tig;
    float b0a = bsum[0 * 128 + ddb], b0b = bsum[0 * 128 + ddb + 1];
    float b1a = bsum[1 * 128 + ddb], b1b = bsum[1 * 128 + ddb + 1];
    float b2a = bsum[2 * 128 + ddb], b2b = bsum[2 * 128 + ddb + 1];
    float b3a = bsum[3 * 128 + ddb], b3b = bsum[3 * 128 + ddb + 1];

    #pragma unroll
    for (int mi = 0; mi < 2; mi++) {
        #pragma unroll
        for (int h = 0; h < 2; h++) {
            int row = bm + wr * 32 + mi * 16 + grp + h * 8;
            size_t off = (size_t)row * D + ddb;
            float2 cc2 = *(float2*)&cst[off];
            float gi0 = acc[mi][0][h * 2 + 0] + b0a, gi1 = acc[mi][0][h * 2 + 1] + b0b;
            float gf0 = acc[mi][1][h * 2 + 0] + b1a, gf1 = acc[mi][1][h * 2 + 1] + b1b;
            float gg0 = acc[mi][2][h * 2 + 0] + b2a, gg1 = acc[mi][2][h * 2 + 1] + b2b;
            float go0 = acc[mi][3][h * 2 + 0] + b3a, go1 = acc[mi][3][h * 2 + 1] + b3b;
            float c20 = sigm(gf0) * cc2.x + sigm(gi0) * tanhf(gg0);
            float c21 = sigm(gf1) * cc2.y + sigm(gi1) * tanhf(gg1);
            *(float2*)&cst[off] = make_float2(c20, c21);
            *(unsigned*)&hnew[off] = pack_bf(sigm(go0) * tanhf(c20),
                                             sigm(go1) * tanhf(c21));
        }
    }
}

// ---------------- vote tail: per-row dot + per-graph mean, one kernel -------------
__global__ void vote_tail(const bf16* __restrict__ v2, const float* __restrict__ w2,
                          const float* __restrict__ b2, const int* __restrict__ n_vars,
                          float* __restrict__ out)
{
    int g = blockIdx.x;
    int warp = threadIdx.x >> 5;
    int lane = threadIdx.x & 31;
    __shared__ float wsh[128];
    for (int i = threadIdx.x; i < 128; i += 256) wsh[i] = w2[i];
    __syncthreads();
    float gsum = 0.f;
    for (int row = g * 2 * NVv + warp; row < (g + 1) * 2 * NVv; row += 8) {
        float p = 0.f;
        #pragma unroll
        for (int w = 0; w < 4; w++) {
            int d = lane + w * 32;
            p += __bfloat162float(v2[(size_t)row * D + d]) * wsh[d];
        }
        #pragma unroll
        for (int s = 16; s > 0; s >>= 1) p += __shfl_down_sync(0xffffffff, p, s);
        if (lane == 0) gsum += p + b2[0];
    }
    __shared__ float red[8];
    if (lane == 0) red[warp] = gsum;
    __syncthreads();
    if (threadIdx.x == 0) {
        float s = 0.f;
        for (int i = 0; i < 8; i++) s += red[i];
        out[g] = s / (2.f * (float)n_vars[g]);
    }
}

// ---------------- host orchestration ----------------
extern "C" void kernel_launch(void* const* d_in, const int* in_sizes, int n_in,
                              void* d_out, int out_size)
{
    const int* edge_src   = (const int*)d_in[0];
    const int* n_vars     = (const int*)d_in[6];
    const float* L_init_w = (const float*)d_in[7];
    const float* L_init_b = (const float*)d_in[8];
    const float* C_init_w = (const float*)d_in[9];
    const float* C_init_b = (const float*)d_in[10];
    const float* lmsg_w   = (const float*)d_in[11];
    const float* lmsg_b   = (const float*)d_in[12];
    const float* cmsg_w   = (const float*)d_in[13];
    const float* cmsg_b   = (const float*)d_in[14];
    const float* lu_wih   = (const float*)d_in[15];
    const float* lu_whh   = (const float*)d_in[16];
    const float* lu_bih   = (const float*)d_in[17];
    const float* lu_bhh   = (const float*)d_in[18];
    const float* cu_wih   = (const float*)d_in[19];
    const float* cu_whh   = (const float*)d_in[20];
    const float* cu_bih   = (const float*)d_in[21];
    const float* cu_bhh   = (const float*)d_in[22];
    const float* vote_w0  = (const float*)d_in[23];
    const float* vote_b0  = (const float*)d_in[24];
    const float* vote_w1  = (const float*)d_in[25];
    const float* vote_b1  = (const float*)d_in[26];
    const float* vote_w2  = (const float*)d_in[27];
    const float* vote_b2  = (const float*)d_in[28];

    bf16 *hl0, *hl1, *hc0, *hc1, *msg, *agg, *wb;
    float *cl, *cc, *bsum;
    int *esrc, *adj, *deg;
    cudaGetSymbolAddress((void**)&hl0,  d_hl);      hl1 = hl0 + LROWS * D;
    cudaGetSymbolAddress((void**)&hc0,  d_hc);      hc1 = hc0 + CROWS * D;
    cudaGetSymbolAddress((void**)&cl,   d_cl);
    cudaGetSymbolAddress((void**)&cc,   d_cc);
    cudaGetSymbolAddress((void**)&msg,  d_msg);
    cudaGetSymbolAddress((void**)&agg,  d_agg);
    cudaGetSymbolAddress((void**)&wb,   d_wb);
    cudaGetSymbolAddress((void**)&bsum, d_bsum);
    cudaGetSymbolAddress((void**)&esrc, d_esrc);
    cudaGetSymbolAddress((void**)&adj,  d_adj);
    cudaGetSymbolAddress((void**)&deg,  d_deg);

    cudaFuncSetAttribute(mlp_fused<3>, cudaFuncAttributeMaxDynamicSharedMemorySize, MLP_SMEM);
    cudaFuncSetAttribute(mlp_fused<2>, cudaFuncAttributeMaxDynamicSharedMemorySize, MLP_SMEM);
    cudaFuncSetAttribute(gate_lstm<256, 0>, cudaFuncAttributeMaxDynamicSharedMemorySize, GATE_SMEM);
    cudaFuncSetAttribute(gate_lstm<384, 1>, cudaFuncAttributeMaxDynamicSharedMemorySize, GATE_SMEM);

    cvt_all<<<(WB_TOTAL + 255) / 256, 256>>>(lmsg_w, cmsg_w, cu_wih, cu_whh,
                                             lu_wih, lu_whh, vote_w0, vote_w1,
                                             cu_bih, cu_bhh, lu_bih, lu_bhh, wb, bsum);
    compact_edges<<<(NEDGE + 255) / 256, 256>>>(edge_src, esrc, deg);
    init_hc<<<CROWS, D>>>(L_init_w, L_init_b, C_init_w, C_init_b, hl0, hc0, cl, cc);
    fill_adj<<<(NEDGE + 255) / 256, 256>>>(esrc, adj, deg);
    sort_adj<<<(LROWS + 255) / 256, 256>>>(adj, deg);

    bf16* hls[2] = { hl0, hl1 };
    bf16* hcs[2] = { hc0, hc1 };

    for (int r = 0; r < ROUNDS; r++) {
        bf16* hlc = hls[r & 1];
        bf16* hln = hls[(r + 1) & 1];
        bf16* hcc = hcs[r & 1];
        bf16* hcn = hcs[(r + 1) & 1];

        mlp_fused<3><<<LROWS / 64, 256, MLP_SMEM>>>(hlc,
            wb + WB_LMSG + 0 * D * D, lmsg_b + 0 * D,
            wb + WB_LMSG + 1 * D * D, lmsg_b + 1 * D,
            wb + WB_LMSG + 2 * D * D, lmsg_b + 2 * D, msg, 0);
        clause_agg<<<CROWS / 4, 256>>>((const unsigned*)msg, esrc, (unsigned*)agg);
        gate_lstm<256, 0><<<dim3(CROWS / 64, 4), 256, GATE_SMEM>>>(agg, hcc,
            wb + WB_CUWIH, D, wb + WB_CUWHH, bsum, hcn, cc);
        mlp_fused<3><<<CROWS / 64, 256, MLP_SMEM>>>(hcn,
            wb + WB_CMSG + 0 * D * D, cmsg_b + 0 * D,
            wb + WB_CMSG + 1 * D * D, cmsg_b + 1 * D,
            wb + WB_CMSG + 2 * D * D, cmsg_b + 2 * D, msg, 0);
        lit_agg<<<LROWS / 4, 256>>>((const unsigned*)msg, adj, deg, (unsigned*)agg);
        gate_lstm<384, 1><<<dim3(LROWS / 64, 4), 256, GATE_SMEM>>>(agg, hlc,
            wb + WB_LUWIH, 2 * D, wb + WB_LUWHH, bsum + 512, hln, cl);
    }

    bf16* hfin = hls[ROUNDS & 1];
    mlp_fused<2><<<LROWS / 64, 256, MLP_SMEM>>>(hfin,
        wb + WB_VOTE0, vote_b0, wb + WB_VOTE1, vote_b1, wb + WB_VOTE1, vote_b1, msg, 1);
    vote_tail<<<NGg, 256>>>(msg, vote_w2, vote_b2, n_vars, (float*)d_out);

    (void)in_sizes; (void)n_in; (void)out_size;
}